// round 8
// baseline (speedup 1.0000x reference)
#include <cuda_runtime.h>
#include <cuda_bf16.h>
#include <math.h>

// CoxPHLoss without sorting:
//   S[t]  = sum_{j: time_j == t} exp(risk_j)         (4096 buckets)
//   L[t]  = log( sum_{t' >= t} S[t'] )               (suffix logsum)
//   nll   = sum_t d_t * L[t] - sum_{i: event_i} risk_i
//
// K1: per-block shared 32-bit histograms, flushed via PLAIN coalesced stores
//     to per-block partial arrays (no global atomics -> no L2 atomic tail).
// K2: massively parallel coalesced reduce of the partials (fixed summation
//     order, deterministic), then last-block-done suffix scan + NLL.

#define NBINS    4096
#define GRID1    296            // 148 SMs x 2 resident = exactly one wave
#define THREADS1 1024
#define GRID2    128            // K2: 128 blocks x 1024 (one wave)

// Scratch (device globals; no allocation allowed)
__device__ float  g_partS[GRID1 * NBINS];   // per-block bucket exp-sums
__device__ int    g_partD[GRID1 * NBINS];   // per-block bucket event counts
__device__ double g_partER[GRID1];          // per-block sum of event risks
__device__ double g_S[NBINS];               // reduced bucket sums
__device__ int    g_Dsum[NBINS];            // reduced event counts
__device__ unsigned int g_count;            // K2 last-block ticket

// ---------------------------------------------------------------------------
// Kernel 1: streaming histogram pass (32-bit shared atomics), plain-store
// flush of per-block partials.
// ---------------------------------------------------------------------------
__global__ __launch_bounds__(THREADS1, 2)
void cox_hist_kernel(const float* __restrict__ risk,
                     const int* __restrict__ time_,
                     const int* __restrict__ event_,
                     int n)
{
    __shared__ float s_S[NBINS];
    __shared__ int   s_D[NBINS];
    __shared__ double s_red[32];

    const int tid = threadIdx.x;
    const int bid = blockIdx.x;
    const int lane = tid & 31, wid = tid >> 5;

    #pragma unroll
    for (int i = tid; i < NBINS; i += THREADS1) {
        s_S[i] = 0.0f;
        s_D[i] = 0;
    }
    __syncthreads();

    double er = 0.0;   // sum of risk over events (this thread)

    const int nvec = n >> 2;
    const float4* r4 = reinterpret_cast<const float4*>(risk);
    const int4*   t4 = reinterpret_cast<const int4*>(time_);
    const int4*   e4 = reinterpret_cast<const int4*>(event_);

    const int gstride = GRID1 * THREADS1;
    const int gtid = bid * THREADS1 + tid;

    // 2-deep unrolled grid-stride loop (front-batched loads -> higher MLP)
    int i = gtid;
    for (; i + gstride < nvec; i += 2 * gstride) {
        float4 ra = r4[i];
        int4   ta = t4[i];
        int4   ea = e4[i];
        float4 rb = r4[i + gstride];
        int4   tb = t4[i + gstride];
        int4   eb = e4[i + gstride];

        int a0 = ta.x & (NBINS - 1), a1 = ta.y & (NBINS - 1);
        int a2 = ta.z & (NBINS - 1), a3 = ta.w & (NBINS - 1);
        int b0 = tb.x & (NBINS - 1), b1 = tb.y & (NBINS - 1);
        int b2 = tb.z & (NBINS - 1), b3 = tb.w & (NBINS - 1);

        atomicAdd(&s_S[a0], __expf(ra.x));
        atomicAdd(&s_S[a1], __expf(ra.y));
        atomicAdd(&s_S[a2], __expf(ra.z));
        atomicAdd(&s_S[a3], __expf(ra.w));
        atomicAdd(&s_S[b0], __expf(rb.x));
        atomicAdd(&s_S[b1], __expf(rb.y));
        atomicAdd(&s_S[b2], __expf(rb.z));
        atomicAdd(&s_S[b3], __expf(rb.w));

        if (ea.x) { atomicAdd(&s_D[a0], 1); er += (double)ra.x; }
        if (ea.y) { atomicAdd(&s_D[a1], 1); er += (double)ra.y; }
        if (ea.z) { atomicAdd(&s_D[a2], 1); er += (double)ra.z; }
        if (ea.w) { atomicAdd(&s_D[a3], 1); er += (double)ra.w; }
        if (eb.x) { atomicAdd(&s_D[b0], 1); er += (double)rb.x; }
        if (eb.y) { atomicAdd(&s_D[b1], 1); er += (double)rb.y; }
        if (eb.z) { atomicAdd(&s_D[b2], 1); er += (double)rb.z; }
        if (eb.w) { atomicAdd(&s_D[b3], 1); er += (double)rb.w; }
    }
    if (i < nvec) {
        float4 r = r4[i];
        int4   t = t4[i];
        int4   e = e4[i];
        int t0 = t.x & (NBINS - 1), t1 = t.y & (NBINS - 1);
        int t2 = t.z & (NBINS - 1), t3 = t.w & (NBINS - 1);
        atomicAdd(&s_S[t0], __expf(r.x));
        atomicAdd(&s_S[t1], __expf(r.y));
        atomicAdd(&s_S[t2], __expf(r.z));
        atomicAdd(&s_S[t3], __expf(r.w));
        if (e.x) { atomicAdd(&s_D[t0], 1); er += (double)r.x; }
        if (e.y) { atomicAdd(&s_D[t1], 1); er += (double)r.y; }
        if (e.z) { atomicAdd(&s_D[t2], 1); er += (double)r.z; }
        if (e.w) { atomicAdd(&s_D[t3], 1); er += (double)r.w; }
    }

    // scalar tail (n not multiple of 4)
    for (int j = (nvec << 2) + gtid; j < n; j += gstride) {
        float r = risk[j];
        int   t = time_[j] & (NBINS - 1);
        atomicAdd(&s_S[t], __expf(r));
        if (event_[j]) { atomicAdd(&s_D[t], 1); er += (double)r; }
    }

    // block-reduce er -> g_partER[bid]
    #pragma unroll
    for (int off = 16; off > 0; off >>= 1)
        er += __shfl_down_sync(0xffffffffu, er, off);
    if (lane == 0) s_red[wid] = er;
    __syncthreads();
    if (wid == 0) {
        double v = s_red[lane];
        #pragma unroll
        for (int off = 16; off > 0; off >>= 1)
            v += __shfl_down_sync(0xffffffffu, v, off);
        if (lane == 0) g_partER[bid] = v;
    }
    __syncthreads();

    // flush shared histograms via plain coalesced stores
    #pragma unroll
    for (int k = tid; k < NBINS; k += THREADS1) {
        g_partS[bid * NBINS + k] = s_S[k];
        g_partD[bid * NBINS + k] = s_D[k];
    }
}

// ---------------------------------------------------------------------------
// Kernel 2: parallel reduce of partials + (last block) suffix scan + NLL.
//   Block B owns bins [B*32, B*32+32). Thread (wid=chunk, lane) sums its
//   chunk of the 296 partials for bin B*32+lane: consecutive lanes read
//   consecutive bins at the same g -> fully coalesced 128B lines.
//   All summation orders fixed -> deterministic.
// ---------------------------------------------------------------------------
__global__ __launch_bounds__(1024, 1)
void cox_reduce_scan_kernel(float* __restrict__ out)
{
    __shared__ double sS[32][33];
    __shared__ int    sD[32][33];
    __shared__ unsigned int s_ticket;

    const int tid = threadIdx.x;
    const int lane = tid & 31, wid = tid >> 5;
    const int bin = blockIdx.x * 32 + lane;

    // chunk boundaries: 296 = 8*10 + 24*9
    int cnt   = (wid < 8) ? 10 : 9;
    int start = (wid < 8) ? wid * 10 : 80 + (wid - 8) * 9;

    double s = 0.0;
    int d = 0;
    for (int k = 0; k < cnt; k++) {
        int g = start + k;
        s += (double)g_partS[g * NBINS + bin];
        d += g_partD[g * NBINS + bin];
    }
    sS[wid][lane] = s;
    sD[wid][lane] = d;
    __syncthreads();

    // warp 0 combines the 32 chunks per bin (fixed order)
    if (wid == 0) {
        double acc = 0.0;
        int dacc = 0;
        #pragma unroll
        for (int k = 0; k < 32; k++) {
            acc  += sS[k][lane];
            dacc += sD[k][lane];
        }
        g_S[bin]    = acc;
        g_Dsum[bin] = dacc;
    }

    // ---- last-block-done: suffix scan + NLL ----
    __threadfence();
    __syncthreads();
    if (tid == 0)
        s_ticket = atomicAdd(&g_count, 1u);
    __syncthreads();
    if (s_ticket != GRID2 - 1)
        return;
    __threadfence();   // acquire side: make other blocks' g_S/g_Dsum visible

    {
        __shared__ double pref[NBINS];
        __shared__ double warpSums[32];
        __shared__ double redbuf[32];
        __shared__ long long dredbuf[32];

        const int base = tid * 4;   // 4 reversed-index elements per thread

        // local inclusive scan (reversed order: a[j] = S[4095-j])
        double v[4];
        int dloc[4];
        double run = 0.0;
        #pragma unroll
        for (int k = 0; k < 4; k++) {
            int t = NBINS - 1 - (base + k);
            run += g_S[t];
            v[k] = run;
            dloc[k] = g_Dsum[t];
        }
        double total = run;

        // warp inclusive scan of per-thread totals
        double x = total;
        #pragma unroll
        for (int off = 1; off < 32; off <<= 1) {
            double y = __shfl_up_sync(0xffffffffu, x, off);
            if (lane >= off) x += y;
        }
        double wexcl = x - total;
        if (lane == 31) warpSums[wid] = x;
        __syncthreads();

        if (wid == 0) {
            double ws = warpSums[lane];
            double xx = ws;
            #pragma unroll
            for (int off = 1; off < 32; off <<= 1) {
                double y = __shfl_up_sync(0xffffffffu, xx, off);
                if (lane >= off) xx += y;
            }
            warpSums[lane] = xx - ws;   // exclusive warp offsets
        }
        __syncthreads();

        double off0 = warpSums[wid] + wexcl;
        #pragma unroll
        for (int k = 0; k < 4; k++)
            pref[base + k] = off0 + v[k];
        __syncthreads();

        // d_t * log(suffix_sum[t]); suffix_sum[t] = pref[4095 - t]
        double c = 0.0;
        long long dtot = 0;
        #pragma unroll
        for (int k = 0; k < 4; k++) {
            int j = base + k;
            int d2 = dloc[k];
            dtot += d2;
            if (d2 > 0) c += (double)d2 * log(pref[j]);
        }
        // subtract event-risk sum (fixed order across tid => deterministic)
        if (tid < GRID1) c -= g_partER[tid];

        #pragma unroll
        for (int off = 16; off > 0; off >>= 1) {
            c    += __shfl_down_sync(0xffffffffu, c, off);
            dtot += __shfl_down_sync(0xffffffffu, dtot, off);
        }
        if (lane == 0) { redbuf[wid] = c; dredbuf[wid] = dtot; }
        __syncthreads();
        if (wid == 0) {
            double cc = redbuf[lane];
            long long dd = dredbuf[lane];
            #pragma unroll
            for (int off = 16; off > 0; off >>= 1) {
                cc += __shfl_down_sync(0xffffffffu, cc, off);
                dd += __shfl_down_sync(0xffffffffu, dd, off);
            }
            if (lane == 0) {
                out[0] = (dd > 0) ? (float)cc : 0.0f;
                g_count = 0u;   // reset for next graph replay
            }
        }
    }
}

// ---------------------------------------------------------------------------
extern "C" void kernel_launch(void* const* d_in, const int* in_sizes, int n_in,
                              void* d_out, int out_size)
{
    const float* risk  = (const float*)d_in[0];
    const int*   time_ = (const int*)d_in[1];
    const int*   event_= (const int*)d_in[2];
    float* out = (float*)d_out;
    int n = in_sizes[0];

    cox_hist_kernel<<<GRID1, THREADS1>>>(risk, time_, event_, n);
    cox_reduce_scan_kernel<<<GRID2, 1024>>>(out);
}

// round 9
// speedup vs baseline: 1.8677x; 1.8677x over previous
#include <cuda_runtime.h>
#include <cuda_bf16.h>
#include <math.h>

// CoxPHLoss without sorting, fused single kernel:
//   S[t]  = sum_{j: time_j == t} exp(risk_j)         (4096 buckets)
//   L[t]  = log( sum_{t' >= t} S[t'] )               (suffix logsum)
//   nll   = sum_t d_t * L[t] - sum_{i: event_i} risk_i
//
// Hist: 32-bit shared atomics (float S, int D) — measured fastest (47us).
// Global combine: fixed-point integer atomics into 8 REPLICATED accumulator
// arrays with per-block ROTATED flush order — decorrelates same-address
// contention at the LTS (same-address L2 atomics serialize ~63x slower than
// spread addresses). Deterministic (integer adds, fixed-order replica sum).
// Last block does the 4096-bin suffix scan + NLL and self-cleans scratch.

#define NBINS    4096
#define GRID1    296            // 148 SMs x 2 resident = exactly one wave
#define THREADS1 1024
#define NREP     8
#define FIX_SCALE 1048576.0f            // 2^20
#define FIX_INV   9.5367431640625e-07   // 2^-20 exact

// Scratch (device globals; zero-initialized at load, self-cleaned per launch)
__device__ unsigned long long g_SfixR[NREP][NBINS];
__device__ int                g_DR[NREP][NBINS];
__device__ double             g_partER[GRID1];
__device__ unsigned int       g_count;

union SmemU {
    struct {
        float S[NBINS];     // 16 KB
        int   D[NBINS];     // 16 KB
    } h;
    double pref[NBINS];     // 32 KB (final-phase alias)
};

__global__ __launch_bounds__(THREADS1, 2)
void cox_fused_kernel(const float* __restrict__ risk,
                      const int* __restrict__ time_,
                      const int* __restrict__ event_,
                      float* __restrict__ out,
                      int n)
{
    __shared__ SmemU u;
    __shared__ double s_red[32];
    __shared__ long long s_dred[32];
    __shared__ double warpSums[32];
    __shared__ unsigned int s_ticket;

    const int tid = threadIdx.x;
    const int bid = blockIdx.x;
    const int lane = tid & 31, wid = tid >> 5;

    #pragma unroll
    for (int i = tid; i < NBINS; i += THREADS1) {
        u.h.S[i] = 0.0f;
        u.h.D[i] = 0;
    }
    __syncthreads();

    double er = 0.0;   // sum of risk over events (this thread)

    const int nvec = n >> 2;
    const float4* r4 = reinterpret_cast<const float4*>(risk);
    const int4*   t4 = reinterpret_cast<const int4*>(time_);
    const int4*   e4 = reinterpret_cast<const int4*>(event_);

    const int gstride = GRID1 * THREADS1;
    const int gtid = bid * THREADS1 + tid;

    for (int i = gtid; i < nvec; i += gstride) {
        float4 r = r4[i];
        int4   t = t4[i];
        int4   e = e4[i];

        int t0 = t.x & (NBINS - 1);
        int t1 = t.y & (NBINS - 1);
        int t2 = t.z & (NBINS - 1);
        int t3 = t.w & (NBINS - 1);

        atomicAdd(&u.h.S[t0], __expf(r.x));
        atomicAdd(&u.h.S[t1], __expf(r.y));
        atomicAdd(&u.h.S[t2], __expf(r.z));
        atomicAdd(&u.h.S[t3], __expf(r.w));

        if (e.x) { atomicAdd(&u.h.D[t0], 1); er += (double)r.x; }
        if (e.y) { atomicAdd(&u.h.D[t1], 1); er += (double)r.y; }
        if (e.z) { atomicAdd(&u.h.D[t2], 1); er += (double)r.z; }
        if (e.w) { atomicAdd(&u.h.D[t3], 1); er += (double)r.w; }
    }

    // scalar tail (n not multiple of 4)
    for (int j = (nvec << 2) + gtid; j < n; j += gstride) {
        float r = risk[j];
        int   t = time_[j] & (NBINS - 1);
        atomicAdd(&u.h.S[t], __expf(r));
        if (event_[j]) { atomicAdd(&u.h.D[t], 1); er += (double)r; }
    }

    // block-reduce er -> g_partER[bid]
    #pragma unroll
    for (int off = 16; off > 0; off >>= 1)
        er += __shfl_down_sync(0xffffffffu, er, off);
    if (lane == 0) s_red[wid] = er;
    __syncthreads();
    if (wid == 0) {
        double v = s_red[lane];
        #pragma unroll
        for (int off = 16; off > 0; off >>= 1)
            v += __shfl_down_sync(0xffffffffu, v, off);
        if (lane == 0) g_partER[bid] = v;
    }
    __syncthreads();

    // flush shared histogram -> replicated global fixed-point accumulators.
    // Replica choice + rotated bin order decorrelate same-address contention.
    {
        const int rep = bid & (NREP - 1);
        const int rot = (bid << 4) & (NBINS - 1);
        for (int i = tid; i < NBINS; i += THREADS1) {
            int j = (i + rot) & (NBINS - 1);
            float s = u.h.S[j];
            int   d = u.h.D[j];
            atomicAdd(&g_SfixR[rep][j], __float2ull_rn(s * FIX_SCALE));
            if (d) atomicAdd(&g_DR[rep][j], d);
        }
    }

    // ---- last-block-done: final suffix scan + NLL + self-clean ----
    __threadfence();
    __syncthreads();
    if (tid == 0)
        s_ticket = atomicAdd(&g_count, 1u);
    __syncthreads();
    if (s_ticket != GRID1 - 1)
        return;

    // Last block: all other blocks' atomics visible.
    const int base = tid * 4;   // 4 reversed-index elements per thread

    // gather replicas (integer sum: exact, deterministic) + local scan
    double v[4];
    int dloc[4];
    double run = 0.0;
    #pragma unroll
    for (int k = 0; k < 4; k++) {
        int t = NBINS - 1 - (base + k);
        unsigned long long fx = 0ull;
        int d = 0;
        #pragma unroll
        for (int rp = 0; rp < NREP; rp++) {
            fx += g_SfixR[rp][t];
            d  += g_DR[rp][t];
        }
        run += (double)fx * FIX_INV;
        v[k] = run;
        dloc[k] = d;
    }
    double total = run;

    // warp inclusive scan of per-thread totals
    double x = total;
    #pragma unroll
    for (int off = 1; off < 32; off <<= 1) {
        double y = __shfl_up_sync(0xffffffffu, x, off);
        if (lane >= off) x += y;
    }
    double wexcl = x - total;
    if (lane == 31) warpSums[wid] = x;
    __syncthreads();

    if (wid == 0) {
        double ws = warpSums[lane];
        double xx = ws;
        #pragma unroll
        for (int off = 1; off < 32; off <<= 1) {
            double y = __shfl_up_sync(0xffffffffu, xx, off);
            if (lane >= off) xx += y;
        }
        warpSums[lane] = xx - ws;   // exclusive warp offsets
    }
    __syncthreads();   // also separates union reuse (hist -> pref)

    double off0 = warpSums[wid] + wexcl;
    #pragma unroll
    for (int k = 0; k < 4; k++)
        u.pref[base + k] = off0 + v[k];
    __syncthreads();

    // contributions: d_t * log(suffix_sum[t]); suffix_sum[t] = pref[4095-t]
    double c = 0.0;
    long long dtot = 0;
    #pragma unroll
    for (int k = 0; k < 4; k++) {
        int j = base + k;
        int d = dloc[k];
        dtot += d;
        if (d > 0) c += (double)d * log(u.pref[j]);
    }
    // subtract event-risk sum (fixed order across tid => deterministic)
    if (tid < GRID1) c -= g_partER[tid];

    #pragma unroll
    for (int off = 16; off > 0; off >>= 1) {
        c    += __shfl_down_sync(0xffffffffu, c, off);
        dtot += __shfl_down_sync(0xffffffffu, dtot, off);
    }
    if (lane == 0) { s_red[wid] = c; s_dred[wid] = dtot; }
    __syncthreads();
    if (wid == 0) {
        double cc = s_red[lane];
        long long dd = s_dred[lane];
        #pragma unroll
        for (int off = 16; off > 0; off >>= 1) {
            cc += __shfl_down_sync(0xffffffffu, cc, off);
            dd += __shfl_down_sync(0xffffffffu, dd, off);
        }
        if (lane == 0)
            out[0] = (dd > 0) ? (float)cc : 0.0f;
    }
    __syncthreads();

    // self-clean scratch for the next graph replay
    unsigned long long* sflat = &g_SfixR[0][0];
    int* dflat = &g_DR[0][0];
    #pragma unroll
    for (int i = tid; i < NREP * NBINS; i += THREADS1) {
        sflat[i] = 0ull;
        dflat[i] = 0;
    }
    if (tid == 0)
        g_count = 0u;
}

// ---------------------------------------------------------------------------
extern "C" void kernel_launch(void* const* d_in, const int* in_sizes, int n_in,
                              void* d_out, int out_size)
{
    const float* risk  = (const float*)d_in[0];
    const int*   time_ = (const int*)d_in[1];
    const int*   event_= (const int*)d_in[2];
    float* out = (float*)d_out;
    int n = in_sizes[0];

    cox_fused_kernel<<<GRID1, THREADS1>>>(risk, time_, event_, out, n);
}

// round 10
// speedup vs baseline: 2.0066x; 1.0744x over previous
#include <cuda_runtime.h>
#include <cuda_bf16.h>
#include <math.h>

// CoxPHLoss without sorting, single cooperative kernel (grid = 148 <= #SMs,
// so all blocks are co-resident and a spin barrier is deadlock-free):
//   S[t]  = sum_{j: time_j == t} exp(risk_j)         (4096 buckets)
//   L[t]  = log( sum_{t' >= t} S[t'] )               (suffix logsum)
//   nll   = sum_t d_t * L[t] - sum_{i: event_i} risk_i
//
// Phase 1: stream + per-block shared 32-bit histograms, PLAIN-STORE flush
//          to per-block partials (the measured-fast path; 2.4 MB total).
// Phase 2: grid spin-barrier, then ALL blocks cooperatively reduce the 148
//          partials (fixed order -> deterministic).
// Phase 3: block 0 waits on arrival counter, does suffix scan + NLL, resets
//          the counters (self-clean for graph replays).

#define NBINS    4096
#define GRIDC    148            // <= #SMs: all blocks co-resident (safe spin)
#define THREADS1 1024
#define BINS_PER_BLOCK 28       // 148*28 = 4144 >= 4096

// Scratch (device globals; counters self-cleaned every launch)
__device__ float        g_partS[GRIDC * NBINS];
__device__ int          g_partD[GRIDC * NBINS];
__device__ double       g_partER[GRIDC];
__device__ double       g_S[NBINS];
__device__ int          g_Dsum[NBINS];
__device__ unsigned int g_bar1;
__device__ unsigned int g_bar2;

union SmemU {
    struct {
        float S[NBINS];     // 16 KB
        int   D[NBINS];     // 16 KB
    } h;
    double pref[NBINS];     // 32 KB (final-phase alias)
};

__global__ __launch_bounds__(THREADS1, 2)
void cox_coop_kernel(const float* __restrict__ risk,
                     const int* __restrict__ time_,
                     const int* __restrict__ event_,
                     float* __restrict__ out,
                     int n)
{
    __shared__ SmemU u;
    __shared__ double s_red[32];
    __shared__ long long s_dred[32];
    __shared__ double warpSums[32];

    const int tid = threadIdx.x;
    const int bid = blockIdx.x;
    const int lane = tid & 31, wid = tid >> 5;

    #pragma unroll
    for (int i = tid; i < NBINS; i += THREADS1) {
        u.h.S[i] = 0.0f;
        u.h.D[i] = 0;
    }
    __syncthreads();

    // ---------------- Phase 1: streaming histogram ----------------
    double er = 0.0;   // sum of risk over events (this thread)

    const int nvec = n >> 2;
    const float4* r4 = reinterpret_cast<const float4*>(risk);
    const int4*   t4 = reinterpret_cast<const int4*>(time_);
    const int4*   e4 = reinterpret_cast<const int4*>(event_);

    const int gstride = GRIDC * THREADS1;
    const int gtid = bid * THREADS1 + tid;

    for (int i = gtid; i < nvec; i += gstride) {
        float4 r = r4[i];
        int4   t = t4[i];
        int4   e = e4[i];

        int t0 = t.x & (NBINS - 1);
        int t1 = t.y & (NBINS - 1);
        int t2 = t.z & (NBINS - 1);
        int t3 = t.w & (NBINS - 1);

        atomicAdd(&u.h.S[t0], __expf(r.x));
        atomicAdd(&u.h.S[t1], __expf(r.y));
        atomicAdd(&u.h.S[t2], __expf(r.z));
        atomicAdd(&u.h.S[t3], __expf(r.w));

        if (e.x) { atomicAdd(&u.h.D[t0], 1); er += (double)r.x; }
        if (e.y) { atomicAdd(&u.h.D[t1], 1); er += (double)r.y; }
        if (e.z) { atomicAdd(&u.h.D[t2], 1); er += (double)r.z; }
        if (e.w) { atomicAdd(&u.h.D[t3], 1); er += (double)r.w; }
    }

    // scalar tail (n not multiple of 4)
    for (int j = (nvec << 2) + gtid; j < n; j += gstride) {
        float r = risk[j];
        int   t = time_[j] & (NBINS - 1);
        atomicAdd(&u.h.S[t], __expf(r));
        if (event_[j]) { atomicAdd(&u.h.D[t], 1); er += (double)r; }
    }

    // block-reduce er -> g_partER[bid]
    #pragma unroll
    for (int off = 16; off > 0; off >>= 1)
        er += __shfl_down_sync(0xffffffffu, er, off);
    if (lane == 0) s_red[wid] = er;
    __syncthreads();
    if (wid == 0) {
        double v = s_red[lane];
        #pragma unroll
        for (int off = 16; off > 0; off >>= 1)
            v += __shfl_down_sync(0xffffffffu, v, off);
        if (lane == 0) g_partER[bid] = v;
    }
    __syncthreads();

    // plain-store flush of the shared histogram (coalesced)
    #pragma unroll
    for (int k = tid; k < NBINS; k += THREADS1) {
        g_partS[bid * NBINS + k] = u.h.S[k];
        g_partD[bid * NBINS + k] = u.h.D[k];
    }

    // ---------------- grid barrier #1 (release/acquire) ----------------
    __threadfence();
    __syncthreads();
    if (tid == 0) {
        atomicAdd(&g_bar1, 1u);
        while (atomicAdd(&g_bar1, 0u) < GRIDC)
            __nanosleep(64);
    }
    __syncthreads();

    // ---------------- Phase 2: cooperative combine ----------------
    // Warp w of block b owns bin b*28 + w (w < 28). Lanes split the 148
    // partials (lane<20 -> 5, else 4; fixed order -> deterministic).
    if (wid < BINS_PER_BLOCK) {
        int bin = bid * BINS_PER_BLOCK + wid;
        if (bin < NBINS) {
            int cnt   = (lane < 20) ? 5 : 4;
            int start = (lane < 20) ? lane * 5 : 100 + (lane - 20) * 4;
            double s = 0.0;
            int d = 0;
            for (int k = 0; k < cnt; k++) {
                int p = start + k;
                s += (double)g_partS[p * NBINS + bin];
                d += g_partD[p * NBINS + bin];
            }
            #pragma unroll
            for (int off = 16; off > 0; off >>= 1) {
                s += __shfl_down_sync(0xffffffffu, s, off);
                d += __shfl_down_sync(0xffffffffu, d, off);
            }
            if (lane == 0) {
                g_S[bin]    = s;
                g_Dsum[bin] = d;
            }
        }
    }

    // ---------------- grid barrier #2 (arrive; only block 0 waits) -----
    __threadfence();
    __syncthreads();
    if (tid == 0)
        atomicAdd(&g_bar2, 1u);
    if (bid != 0)
        return;
    if (tid == 0) {
        while (atomicAdd(&g_bar2, 0u) < GRIDC)
            __nanosleep(64);
    }
    __syncthreads();

    // ---------------- Phase 3: suffix scan + NLL (block 0) -------------
    const int base = tid * 4;   // 4 reversed-index elements per thread

    double v[4];
    int dloc[4];
    double run = 0.0;
    #pragma unroll
    for (int k = 0; k < 4; k++) {
        int t = NBINS - 1 - (base + k);
        run += g_S[t];
        v[k] = run;
        dloc[k] = g_Dsum[t];
    }
    double total = run;

    // warp inclusive scan of per-thread totals
    double x = total;
    #pragma unroll
    for (int off = 1; off < 32; off <<= 1) {
        double y = __shfl_up_sync(0xffffffffu, x, off);
        if (lane >= off) x += y;
    }
    double wexcl = x - total;
    if (lane == 31) warpSums[wid] = x;
    __syncthreads();

    if (wid == 0) {
        double ws = warpSums[lane];
        double xx = ws;
        #pragma unroll
        for (int off = 1; off < 32; off <<= 1) {
            double y = __shfl_up_sync(0xffffffffu, xx, off);
            if (lane >= off) xx += y;
        }
        warpSums[lane] = xx - ws;   // exclusive warp offsets
    }
    __syncthreads();   // also separates union reuse (hist -> pref)

    double off0 = warpSums[wid] + wexcl;
    #pragma unroll
    for (int k = 0; k < 4; k++)
        u.pref[base + k] = off0 + v[k];
    __syncthreads();

    // d_t * log(suffix_sum[t]); suffix_sum[t] = pref[4095 - t]
    double c = 0.0;
    long long dtot = 0;
    #pragma unroll
    for (int k = 0; k < 4; k++) {
        int j = base + k;
        int d = dloc[k];
        dtot += d;
        if (d > 0) c += (double)d * log(u.pref[j]);
    }
    // subtract event-risk sum (fixed order across tid => deterministic)
    if (tid < GRIDC) c -= g_partER[tid];

    #pragma unroll
    for (int off = 16; off > 0; off >>= 1) {
        c    += __shfl_down_sync(0xffffffffu, c, off);
        dtot += __shfl_down_sync(0xffffffffu, dtot, off);
    }
    if (lane == 0) { s_red[wid] = c; s_dred[wid] = dtot; }
    __syncthreads();
    if (wid == 0) {
        double cc = s_red[lane];
        long long dd = s_dred[lane];
        #pragma unroll
        for (int off = 16; off > 0; off >>= 1) {
            cc += __shfl_down_sync(0xffffffffu, cc, off);
            dd += __shfl_down_sync(0xffffffffu, dd, off);
        }
        if (lane == 0) {
            out[0] = (dd > 0) ? (float)cc : 0.0f;
            g_bar1 = 0u;           // self-clean for next graph replay
            g_bar2 = 0u;
        }
    }
}

// ---------------------------------------------------------------------------
extern "C" void kernel_launch(void* const* d_in, const int* in_sizes, int n_in,
                              void* d_out, int out_size)
{
    const float* risk  = (const float*)d_in[0];
    const int*   time_ = (const int*)d_in[1];
    const int*   event_= (const int*)d_in[2];
    float* out = (float*)d_out;
    int n = in_sizes[0];

    cox_coop_kernel<<<GRIDC, THREADS1>>>(risk, time_, event_, out, n);
}